// round 5
// baseline (speedup 1.0000x reference)
#include <cuda_runtime.h>

// ---------------- problem constants ----------------
#define B 4
#define T_TOTAL 35968706LL          // sum of all 52 weight-tensor sizes (= 4*NQ + 2)
#define NQ 8992176LL                // full float4 count per row
#define NV (T_TOTAL / 2)            // float2 count per row

// ---------------- device scratch (no allocs allowed) ----------------
__device__ float g_c1[4 * 4  * 112 * 112];
__device__ float g_c2[4 * 8  * 56  * 56];
__device__ float g_c3[4 * 16 * 28  * 28];
__device__ float g_c4[4 * 32 * 14  * 14];
__device__ float g_c5[4 * 64 * 7   * 7];
__device__ float g_q[64];           // q[b][j], b*16+j

// ---------------- split-K conv: k=4, s=2, p=1 ----------------
template<int CIN, int G, bool LRELU>
__global__ void __launch_bounds__(256)
conv_split(const float* __restrict__ x, const float* __restrict__ w,
           const float* __restrict__ bias, float* __restrict__ y,
           int Hin, int Win, int Cout, int Hout, int Wout)
{
    constexpr int OPT = 256 / G;      // outputs per block
    constexpr int CPG = CIN / G;      // channels per partial group
    const int tid = threadIdx.x;
    const int g   = tid / OPT;
    const int ol  = tid % OPT;

    long long oidx = (long long)blockIdx.x * OPT + ol;
    int ow = (int)(oidx % Wout); long long t = oidx / Wout;
    int oh = (int)(t % Hout);    t /= Hout;
    int co = (int)(t % Cout);
    int n  = (int)(t / Cout);

    const int ih0 = oh * 2 - 1, iw0 = ow * 2 - 1;
    const float* xn = x + ((long long)n * CIN + g * CPG) * Hin * Win;
    const float* wc = w + ((long long)co * CIN + g * CPG) * 16;

    float acc = 0.f;
    #pragma unroll
    for (int ci = 0; ci < CPG; ci++) {
        const float* xc = xn + ci * Hin * Win;
        const float* wk = wc + ci * 16;
        #pragma unroll
        for (int kh = 0; kh < 4; kh++) {
            int ih = ih0 + kh;
            if ((unsigned)ih >= (unsigned)Hin) continue;
            const float* xr = xc + ih * Win;
            #pragma unroll
            for (int kw = 0; kw < 4; kw++) {
                int iw = iw0 + kw;
                if ((unsigned)iw < (unsigned)Win)
                    acc = fmaf(xr[iw], wk[kh * 4 + kw], acc);
            }
        }
    }

    if (G == 1) {
        acc += bias[co];
        if (LRELU) acc = (acc >= 0.f) ? acc : 0.01f * acc;
        y[oidx] = acc;
    } else {
        __shared__ float s[256];
        s[tid] = acc;
        __syncthreads();
        if (g == 0) {
            float sum = acc;
            #pragma unroll
            for (int j = 1; j < G; j++) sum += s[j * OPT + ol];
            sum += bias[co];
            if (LRELU) sum = (sum >= 0.f) ? sum : 0.01f * sum;
            y[oidx] = sum;
        }
    }
}

// ---------------- head: pool -> fc1 -> fc2 -> VQ -> q, loss ----------------
__global__ void head_k(const float* __restrict__ conv5,
                       const float* __restrict__ fc1w, const float* __restrict__ fc1b,
                       const float* __restrict__ fc2w, const float* __restrict__ fc2b,
                       const float* __restrict__ emb,
                       float* __restrict__ loss_out)
{
    __shared__ float sx[4][64];
    __shared__ float sh[4][16];
    __shared__ float se[4][16];
    __shared__ int   sidx[4];
    __shared__ float sred[64];
    int tid = threadIdx.x;                 // blockDim.x == 256

    // adaptive avg pool over 7x7
    {
        int b = tid >> 6, c = tid & 63;
        const float* p = conv5 + (b * 64 + c) * 49;
        float s = 0.f;
        #pragma unroll
        for (int i = 0; i < 49; i++) s += p[i];
        sx[b][c] = s * (1.f / 49.f);
    }
    __syncthreads();

    // fc1 (64->16) + lrelu
    if (tid < 64) {
        int b = tid >> 4, j = tid & 15;
        float s = fc1b[j];
        #pragma unroll
        for (int k = 0; k < 64; k++) s += sx[b][k] * fc1w[j * 64 + k];
        sh[b][j] = (s >= 0.f) ? s : 0.01f * s;
    }
    __syncthreads();

    // fc2 (16->16)
    if (tid < 64) {
        int b = tid >> 4, j = tid & 15;
        float s = fc2b[j];
        #pragma unroll
        for (int k = 0; k < 16; k++) s += sh[b][k] * fc2w[j * 16 + k];
        se[b][j] = s;
    }
    __syncthreads();

    // VQ nearest-codebook (first-min semantics like jnp.argmin)
    if (tid < 4) {
        int b = tid;
        float ee = 0.f;
        #pragma unroll
        for (int j = 0; j < 16; j++) ee += se[b][j] * se[b][j];
        float best = __int_as_float(0x7f800000);   // +inf
        int bi = 0;
        for (int c = 0; c < 4; c++) {
            float s2 = 0.f, dot = 0.f;
            #pragma unroll
            for (int j = 0; j < 16; j++) {
                float w = emb[c * 16 + j];
                s2  += w * w;
                dot += w * se[b][j];
            }
            float d = ee + s2 - 2.f * dot;
            if (d < best) { best = d; bi = c; }
        }
        sidx[b] = bi;
    }
    __syncthreads();

    // q + loss = 1.25 * mean((q - e)^2)
    if (tid < 64) {
        int b = tid >> 4, j = tid & 15;
        float qv = emb[sidx[b] * 16 + j];
        g_q[tid] = qv;
        float diff = qv - se[b][j];
        sred[tid] = diff * diff;
    }
    __syncthreads();
    if (tid == 0) {
        float s = 0.f;
        for (int i = 0; i < 64; i++) s += sred[i];
        *loss_out = 1.25f * s * (1.f / 64.f);
    }
}

// ---------------- the big streaming GEMM: out = q @ W_all ----------------
// Each thread covers 4 consecutive floats per row. Row base offsets alternate
// alignment because T ≡ 2 (mod 4):
//   even-k W rows / output rows 0,2 : 16B-aligned -> float4 ops (512B/warp/instr)
//   odd-k  W rows / output rows 1,3 : 8B-aligned  -> two float2 ops that jointly
//     cover the same contiguous 512B span (same L2 sectors -> no extra DRAM traffic)
__global__ void __launch_bounds__(256)
gemm_k(const float* __restrict__ W, float* __restrict__ out)
{
    __shared__ float sq[64];
    if (threadIdx.x < 64) sq[threadIdx.x] = g_q[threadIdx.x];
    __syncthreads();

    long long t4 = (long long)blockIdx.x * blockDim.x + threadIdx.x;  // float4 index
    if (t4 > NQ) return;

    if (t4 < NQ) {
        long long f0 = t4 * 4;      // float offset within a row
        float4 a0 = {0,0,0,0}, a1 = {0,0,0,0}, a2 = {0,0,0,0}, a3 = {0,0,0,0};

        #pragma unroll
        for (int k = 0; k < 16; k++) {
            const float* p = W + (long long)k * T_TOTAL + f0;
            float4 w;
            if ((k & 1) == 0) {
                w = __ldcs((const float4*)p);           // 16B aligned
            } else {
                float2 lo = __ldcs((const float2*)p);   // 8B aligned
                float2 hi = __ldcs((const float2*)(p + 2));
                w = make_float4(lo.x, lo.y, hi.x, hi.y);
            }
            float q0 = sq[k], q1 = sq[16 + k], q2 = sq[32 + k], q3 = sq[48 + k];
            a0.x = fmaf(q0, w.x, a0.x); a0.y = fmaf(q0, w.y, a0.y);
            a0.z = fmaf(q0, w.z, a0.z); a0.w = fmaf(q0, w.w, a0.w);
            a1.x = fmaf(q1, w.x, a1.x); a1.y = fmaf(q1, w.y, a1.y);
            a1.z = fmaf(q1, w.z, a1.z); a1.w = fmaf(q1, w.w, a1.w);
            a2.x = fmaf(q2, w.x, a2.x); a2.y = fmaf(q2, w.y, a2.y);
            a2.z = fmaf(q2, w.z, a2.z); a2.w = fmaf(q2, w.w, a2.w);
            a3.x = fmaf(q3, w.x, a3.x); a3.y = fmaf(q3, w.y, a3.y);
            a3.z = fmaf(q3, w.z, a3.z); a3.w = fmaf(q3, w.w, a3.w);
        }

        float* p0 = out + f0;                       // row 0: 16B aligned
        float* p1 = out + T_TOTAL + f0;             // row 1: 8B aligned
        float* p2 = out + 2 * T_TOTAL + f0;         // row 2: 16B aligned
        float* p3 = out + 3 * T_TOTAL + f0;         // row 3: 8B aligned
        __stcs((float4*)p0, a0);
        __stcs((float2*)p1, make_float2(a1.x, a1.y));
        __stcs((float2*)(p1 + 2), make_float2(a1.z, a1.w));
        __stcs((float4*)p2, a2);
        __stcs((float2*)p3, make_float2(a3.x, a3.y));
        __stcs((float2*)(p3 + 2), make_float2(a3.z, a3.w));
    } else {
        // tail: last 2 floats of each row (T = 4*NQ + 2); all 8B aligned
        long long f0 = NQ * 4;
        float2 a0 = {0,0}, a1 = {0,0}, a2 = {0,0}, a3 = {0,0};
        #pragma unroll
        for (int k = 0; k < 16; k++) {
            float2 w = __ldcs((const float2*)(W + (long long)k * T_TOTAL + f0));
            float q0 = sq[k], q1 = sq[16 + k], q2 = sq[32 + k], q3 = sq[48 + k];
            a0.x = fmaf(q0, w.x, a0.x); a0.y = fmaf(q0, w.y, a0.y);
            a1.x = fmaf(q1, w.x, a1.x); a1.y = fmaf(q1, w.y, a1.y);
            a2.x = fmaf(q2, w.x, a2.x); a2.y = fmaf(q2, w.y, a2.y);
            a3.x = fmaf(q3, w.x, a3.x); a3.y = fmaf(q3, w.y, a3.y);
        }
        __stcs((float2*)(out + f0),                a0);
        __stcs((float2*)(out + T_TOTAL + f0),      a1);
        __stcs((float2*)(out + 2 * T_TOTAL + f0),  a2);
        __stcs((float2*)(out + 3 * T_TOTAL + f0),  a3);
    }
}

// ---------------- launch ----------------
extern "C" void kernel_launch(void* const* d_in, const int* in_sizes, int n_in,
                              void* d_out, int out_size)
{
    const float* rgb   = (const float*)d_in[0];
    const float* cw1   = (const float*)d_in[1];
    const float* cb1   = (const float*)d_in[2];
    const float* cw2   = (const float*)d_in[3];
    const float* cb2   = (const float*)d_in[4];
    const float* cw3   = (const float*)d_in[5];
    const float* cb3   = (const float*)d_in[6];
    const float* cw4   = (const float*)d_in[7];
    const float* cb4   = (const float*)d_in[8];
    const float* cw5   = (const float*)d_in[9];
    const float* cb5   = (const float*)d_in[10];
    const float* fc1w  = (const float*)d_in[11];
    const float* fc1b  = (const float*)d_in[12];
    const float* fc2w  = (const float*)d_in[13];
    const float* fc2b  = (const float*)d_in[14];
    const float* emb   = (const float*)d_in[15];
    const float* Wall  = (const float*)d_in[16];
    float* out = (float*)d_out;

    float *c1, *c2, *c3, *c4, *c5;
    cudaGetSymbolAddress((void**)&c1, g_c1);
    cudaGetSymbolAddress((void**)&c2, g_c2);
    cudaGetSymbolAddress((void**)&c3, g_c3);
    cudaGetSymbolAddress((void**)&c4, g_c4);
    cudaGetSymbolAddress((void**)&c5, g_c5);

    conv_split<3, 1,  true ><<<784, 256>>>(rgb, cw1, cb1, c1, 224, 224, 4, 112, 112);
    conv_split<4, 2,  true ><<<784, 256>>>(c1,  cw2, cb2, c2, 112, 112, 8,  56,  56);
    conv_split<8, 4,  true ><<<784, 256>>>(c2,  cw3, cb3, c3,  56,  56, 16, 28,  28);
    conv_split<16,8,  true ><<<784, 256>>>(c3,  cw4, cb4, c4,  28,  28, 32, 14,  14);
    conv_split<32,16, false><<<784, 256>>>(c4,  cw5, cb5, c5,  14,  14, 64,  7,   7);

    // head -> q, loss (loss lives at the last output element)
    head_k<<<1, 256>>>(c5, fc1w, fc1b, fc2w, fc2b, emb, out + (long long)out_size - 1);

    // big streaming GEMM: one float4 span per thread (+1 thread for the 2-float tail)
    const int TB = 256;
    long long nthreads = NQ + 1;
    long long nblocks  = (nthreads + TB - 1) / TB;
    gemm_k<<<(unsigned)nblocks, TB>>>(Wall, out);
}